// round 13
// baseline (speedup 1.0000x reference)
#include <cuda_runtime.h>
#include <math.h>

#define NN 256
#define MM 255

// Scratch (no cudaMalloc allowed)
__device__ float  g_gp[4][NN * NN];   // partial Gram per 64-dim chunk
__device__ float  g_nrm[NN];          // squared norms of stacked rows
__device__ double g_acc;
__device__ int    g_done = 0;         // completion counter (self-resetting)

__device__ __forceinline__ float tanha(float x) {
    float y;
    asm("tanh.approx.f32 %0, %1;" : "=f"(y) : "f"(x));
    return y;
}
__device__ __forceinline__ int imin(int a, int b) { return a < b ? a : b; }
__device__ __forceinline__ int imax(int a, int b) { return a > b ? a : b; }

// first index in [lo,hi) with arr[idx] > v (arr ascending)
__device__ __forceinline__ int lbgt(const float* arr, int lo, int hi, float v) {
    while (lo < hi) {
        const int mid = (lo + hi) >> 1;
        if (arr[mid] > v) hi = mid; else lo = mid + 1;
    }
    return lo;
}

// ---------------------------------------------------------------------------
// Kernel 1 (unchanged): blocks 0..127: partial Gram over a 64-dim chunk,
// 64x32 tile, 4x2 register tiling. Blocks 128..159: squared norms.
// ---------------------------------------------------------------------------
__global__ void gram_kernel(const float* __restrict__ features) {
    __shared__ float As[64 * 68];
    __shared__ float Bs[64 * 34];

    const int bid = blockIdx.x;
    const int tid = threadIdx.x;

    if (bid >= 128) {                       // norms: 32 blocks x 8 rows
        const int w = tid >> 5, lane = tid & 31;
        const int r = ((bid - 128) << 3) + w;
        const float4* row = (const float4*)(features + ((((r & 127) << 1) + (r >> 7)) << 8));
        const float4 a = row[lane];
        const float4 b = row[lane + 32];
        float s = a.x * a.x + a.y * a.y + a.z * a.z + a.w * a.w
                + b.x * b.x + b.y * b.y + b.z * b.z + b.w * b.w;
#pragma unroll
        for (int o = 16; o; o >>= 1) s += __shfl_xor_sync(0xFFFFFFFFu, s, o);
        if (lane == 0) g_nrm[r] = s;
        return;
    }

    const int jt = (bid & 7) << 5;
    const int it = ((bid >> 3) & 3) << 6;
    const int ch = bid >> 5;                // 0..3

    if (bid == 0 && tid == 0) g_acc = 0.0;

    {   // A: 64 rows x 64 dims -> K-major transpose
        const int r  = tid >> 2;
        const int q0 = tid & 3;
        const int gi = it + r;
        const float* fa = &features[(((gi & 127) << 1) + (gi >> 7)) * 256 + (ch << 6)];
#pragma unroll
        for (int h = 0; h < 4; h++) {
            const int f4 = q0 + (h << 2);
            const float4 a = *(const float4*)&fa[f4 << 2];
            const int k0 = f4 << 2;
            As[(k0 + 0) * 68 + r] = a.x;
            As[(k0 + 1) * 68 + r] = a.y;
            As[(k0 + 2) * 68 + r] = a.z;
            As[(k0 + 3) * 68 + r] = a.w;
        }
    }
    {   // B: 32 rows x 64 dims -> K-major transpose
        const int r  = tid >> 3;
        const int q0 = tid & 7;
        const int gj = jt + r;
        const float* fb = &features[(((gj & 127) << 1) + (gj >> 7)) * 256 + (ch << 6)];
#pragma unroll
        for (int h = 0; h < 2; h++) {
            const int f4 = q0 + (h << 3);
            const float4 b = *(const float4*)&fb[f4 << 2];
            const int k0 = f4 << 2;
            Bs[(k0 + 0) * 34 + r] = b.x;
            Bs[(k0 + 1) * 34 + r] = b.y;
            Bs[(k0 + 2) * 34 + r] = b.z;
            Bs[(k0 + 3) * 34 + r] = b.w;
        }
    }
    __syncthreads();

    const int a4 = tid >> 4;
    const int tx = tid & 15;
    float c00 = 0, c01 = 0, c10 = 0, c11 = 0;
    float c20 = 0, c21 = 0, c30 = 0, c31 = 0;
#pragma unroll
    for (int k = 0; k < 64; k++) {
        const float4 av = *(const float4*)&As[k * 68 + (a4 << 2)];
        const float2 bv = *(const float2*)&Bs[k * 34 + (tx << 1)];
        c00 = fmaf(av.x, bv.x, c00);  c01 = fmaf(av.x, bv.y, c01);
        c10 = fmaf(av.y, bv.x, c10);  c11 = fmaf(av.y, bv.y, c11);
        c20 = fmaf(av.z, bv.x, c20);  c21 = fmaf(av.z, bv.y, c21);
        c30 = fmaf(av.w, bv.x, c30);  c31 = fmaf(av.w, bv.y, c31);
    }
    const int r0 = it + (a4 << 2);
    const int c0 = jt + (tx << 1);
    *(float2*)&g_gp[ch][(r0 + 0) * NN + c0] = make_float2(c00, c01);
    *(float2*)&g_gp[ch][(r0 + 1) * NN + c0] = make_float2(c10, c11);
    *(float2*)&g_gp[ch][(r0 + 2) * NN + c0] = make_float2(c20, c21);
    *(float2*)&g_gp[ch][(r0 + 3) * NN + c0] = make_float2(c30, c31);
}

// ---------------------------------------------------------------------------
// Kernel 2: 128 blocks x 512 threads = TWO independent rows per block
// (half = tid>>8), each half identical to the R12 per-row algorithm with its
// own smem region and its own named barrier (bar.sync half+1, 256). One clean
// wave on 148 SMs; 16 warps/SM interleave two rows' latency chains.
// ---------------------------------------------------------------------------
#define HBAR() asm volatile("bar.sync %0, 256;" :: "r"(half + 1) : "memory")

__global__ void __launch_bounds__(512, 1)
main_kernel(const int* __restrict__ labels, float* __restrict__ out) {
    __shared__ float4 sJR[2][NN];     // rank-ordered {2E, q, ladf, sgnf}
    __shared__ float  sZR[2][NN];     // rank-ordered z
    __shared__ float  sRH[2][NN];     // place-ordered rh (ascending per segment)
    __shared__ float  sX[2][NN];      // place-ordered 2E -> segmented suffix sums
    __shared__ float  sU[2][NN];      // place-ordered u
    __shared__ int    cntL[2][8][16], cntK[2][8][32];
    __shared__ int    sumL[2][16], sumK[2][32];
    __shared__ int    histBase[2][16];
    __shared__ int    BP[2][10], CP[2][10], BM[2][10], CM[2][10];
    __shared__ int    sNP[2], sNE[2], sB[2];
    __shared__ float  sZmaxW[2][8], sZminW[2][8];
    __shared__ float  wsum[2][8];

    const int tid  = threadIdx.x;
    const int half = tid >> 8;          // 0 or 1 (row within block)
    const int htid = tid & 255;         // thread index within half
    const int i    = (blockIdx.x << 1) + half;
    const int lane = tid & 31;
    const int wid  = htid >> 5;         // warp index within half (0..7)
    const unsigned lt = (1u << lane) - 1u;
    const int li   = labels[i & 127];

    cntK[half][wid][lane] = 0;
    if (htid < 128) cntL[half][htid >> 4][htid & 15] = 0;
    HBAR();

    // ---- phase 1: per-j basics (j = htid), coalesced; z min/max reduce ----
    float z = 0.0f, sgn = 0.0f;
    int lad = 15, key = 31;
    if (htid < MM) {
        const int c = htid + (htid >= i);
        float gij = 0.0f;
#pragma unroll
        for (int ch = 0; ch < 4; ch++) gij += g_gp[ch][i * NN + c];
        z = sqrtf(fmaxf(fmaf(-2.0f, gij, g_nrm[i] + g_nrm[c]), 0.0f));
        const int ld = li - labels[c & 127];
        lad = ld < 0 ? -ld : ld;
        key = (lad == 0) ? 0 : (ld > 0 ? lad : 16 + lad);
        sgn = (float)((ld > 0) - (ld < 0));
    }
    const unsigned mL = __match_any_sync(0xFFFFFFFFu, lad);
    const unsigned mK = __match_any_sync(0xFFFFFFFFu, key);
    const int tieL = __popc(mL & lt);
    const int tieK = __popc(mK & lt);
    cntL[half][wid][lad & 15] = __popc(mL);
    cntK[half][wid][key]      = __popc(mK);
    {
        float zx = (htid < MM) ? z : -1e30f;
        float zn = (htid < MM) ? z :  1e30f;
#pragma unroll
        for (int o = 16; o; o >>= 1) {
            zx = fmaxf(zx, __shfl_xor_sync(0xFFFFFFFFu, zx, o));
            zn = fminf(zn, __shfl_xor_sync(0xFFFFFFFFu, zn, o));
        }
        if (lane == 0) { sZmaxW[half][wid] = zx; sZminW[half][wid] = zn; }
    }
    HBAR();

    if (htid < 16) { int s = 0;
#pragma unroll
        for (int g = 0; g < 8; g++) s += cntL[half][g][htid];
        sumL[half][htid] = s; }
    if (htid >= 32 && htid < 64) { int s = 0; const int b = htid - 32;
#pragma unroll
        for (int g = 0; g < 8; g++) s += cntK[half][g][b];
        sumK[half][b] = s; }
    HBAR();

    if (htid == 0) {
        int run = 0;
#pragma unroll
        for (int b = 0; b < 16; b++) { histBase[half][b] = run; run += sumL[half][b]; }
        run = 0;
#pragma unroll
        for (int b = 1; b <= 9; b++) { BP[half][b] = run; CP[half][b] = sumK[half][b]; run += sumK[half][b]; }
        sNP[half] = run;
#pragma unroll
        for (int b = 1; b <= 9; b++) { BM[half][b] = run; CM[half][b] = sumK[half][16 + b]; run += sumK[half][16 + b]; }
        sNE[half] = run;
        BP[half][0] = 0; CP[half][0] = 0; BM[half][0] = sNP[half]; CM[half][0] = 0;
        float zx = -1e30f, zn = 1e30f;
#pragma unroll
        for (int w = 0; w < 8; w++) { zx = fmaxf(zx, sZmaxW[half][w]); zn = fminf(zn, sZminW[half][w]); }
        int Bv = (int)ceilf((12.0f + 0.5f * (zx - zn)) * 0.2f) - 1;
        sB[half] = imax(Bv, 1);
    }
    HBAR();

    // ---- phase 2: ranks + dual placement (segment-ordered + rank-ordered) --
    if (htid < MM) {
        int tl = tieL, tk = tieK;
        for (int gg = 0; gg < wid; gg++) { tl += cntL[half][gg][lad]; tk += cntK[half][gg][key]; }
        const int rank = histBase[half][lad] + tl;
        const float rh = 5.0f * (float)rank;     // (rank/delta)/2
        int place;
        if (key == 0)       place = sNE[half] + tk;
        else if (key < 16)  place = BP[half][key] + tk;
        else                place = BM[half][key - 16] + tk;
        const float u = sgn * z;
        const float E2 = 2.0f * __expf(-u);
        sRH[half][place] = rh;
        sX[half][place]  = E2;
        sU[half][place]  = u;
        sJR[half][rank]  = make_float4(E2, fmaf(-0.5f, u, rh), (float)lad, sgn);
        sZR[half][rank]  = z;
    } else {
        sX[half][htid] = 0.0f;      // htid == 255: unused slot, keep scan clean
    }
    HBAR();

    // ---- phase 2.5: segmented suffix scan of sX (resets at NP, NE) ----
    const int NPc = sNP[half], NEc = sNE[half];
    const int myseg = (htid < NPc) ? 0 : ((htid < NEc) ? 1 : 2);
#pragma unroll
    for (int off = 1; off < NN; off <<= 1) {
        const int pp = htid + off;
        float t = 0.0f;
        if (pp < NN) {
            const int ps = (pp < NPc) ? 0 : ((pp < NEc) ? 1 : 2);
            if (ps == myseg) t = sX[half][pp];
        }
        HBAR();
        sX[half][htid] += t;
        HBAR();
    }

    // ---- phase 3: per k, processed in rank order (kq = rank of k) ----
    float term = 0.0f;
    if (htid < MM) {
        const int kq = htid;
        const float4 kr = sJR[half][kq];
        const float ladkf = kr.z;
        const int   ladk  = (int)ladkf;
        const float zk  = sZR[half][kq];
        const float rhk = 5.0f * (float)kq;
        const float epk = __expf(zk);
        const float enk = __expf(-zk);
        const float epkH = 0.5f * epk;
        const float enkH = 0.5f * enk;
        const int Bv = sB[half];
        const float thrHi = 5.0f * (float)(kq + Bv) + 2.5f;

        // saturated mass (weight exactly 2) for rank >= kq + Bv + 1
        const int iP = lbgt(sRH[half], 0,   NPc, thrHi);
        const int iM = lbgt(sRH[half], NPc, NEc, thrHi);
        const int i0 = lbgt(sRH[half], NEc, MM,  thrHi);

        float neg = 1.0f;                   // exact j==k contribution
        float pos = 0.0f;
        if (iP < NPc) neg += epk * sX[half][iP];
        if (iM < NEc) neg += enk * sX[half][iM];
        if (ladk != 0) neg += 2.0f * (float)(MM - i0);

        // exact band: ranks [kq-Bv, kq+Bv], lad != ladk (also excludes j==k)
        const float zkH = 0.5f * zk;
        const int rlo = imax(kq - Bv, 0);
        const int rhi = imin(kq + Bv, MM - 1);
        for (int r = rlo; r <= rhi; r++) {
            const float4 t = sJR[half][r];
            if (t.z == ladkf) continue;
            const float sel = (t.w > 0.0f) ? epkH : ((t.w < 0.0f) ? enkH : 0.5f);
            const float emd = t.x * sel;
            const float arg = fmaf(zkH, t.w, t.y - rhk);
            const float tn  = tanha(arg);
            neg += fmaf(emd, tn, emd);
        }

        // eq-lad runs: remove saturated additions, add exact pos terms
        if (ladk != 0) {
            const int loP = BP[half][ladk], hiP = loP + CP[half][ladk];
            int a = imax(loP, iP);
            if (a < hiP) {
                const float hv = (hiP < NPc) ? sX[half][hiP] : 0.0f;
                neg -= epk * (sX[half][a] - hv);
            }
            for (int p = loP; p < hiP; p++) {
                const float ad = fabsf(sU[half][p] - zk);
                pos += fmaf(ad, tanha(fmaf(0.5f, ad, -0.05f)), ad);
            }
            const int loM = BM[half][ladk], hiM = loM + CM[half][ladk];
            a = imax(loM, iM);
            if (a < hiM) {
                const float hv = (hiM < NEc) ? sX[half][hiM] : 0.0f;
                neg -= enk * (sX[half][a] - hv);
            }
            for (int p = loM; p < hiM; p++) {
                const float ad = fabsf(sU[half][p] + zk);
                pos += fmaf(ad, tanha(fmaf(0.5f, ad, -0.05f)), ad);
            }
        }
        term = pos + logf(neg);
    }

    // ---- reduce + fused finalize (per half) ----
#pragma unroll
    for (int o = 16; o; o >>= 1) term += __shfl_xor_sync(0xFFFFFFFFu, term, o);
    if (lane == 0) wsum[half][wid] = term;
    HBAR();
    if (htid == 0) {
        float s = 0.0f;
#pragma unroll
        for (int w = 0; w < 8; w++) s += wsum[half][w];
        atomicAdd(&g_acc, (double)s);
        __threadfence();
        const int old = atomicAdd(&g_done, 1);
        if (old == NN - 1) {                // last half finalizes (256 halves)
            g_done = 0;                     // reset for next graph replay
            out[0] = (float)(g_acc / (double)(NN * MM));
        }
    }
}

extern "C" void kernel_launch(void* const* d_in, const int* in_sizes, int n_in,
                              void* d_out, int out_size) {
    const float* features = (const float*)d_in[0];   // [128,2,256] f32
    const int*   labels   = (const int*)d_in[1];     // [128,1] i32
    float*       out      = (float*)d_out;           // scalar f32

    gram_kernel<<<160, 256>>>(features);
    main_kernel<<<128, 512>>>(labels, out);
}

// round 14
// speedup vs baseline: 1.1052x; 1.1052x over previous
#include <cuda_runtime.h>
#include <math.h>

#define NN 256
#define MM 255

// Scratch (no cudaMalloc allowed)
__device__ float  g_gp[4][NN * NN];   // partial Gram per 64-dim chunk
__device__ float  g_nrm[NN];          // squared norms of stacked rows
__device__ double g_acc;
__device__ int    g_done = 0;         // completion counter (self-resetting)

__device__ __forceinline__ float tanha(float x) {
    float y;
    asm("tanh.approx.f32 %0, %1;" : "=f"(y) : "f"(x));
    return y;
}
__device__ __forceinline__ int imin(int a, int b) { return a < b ? a : b; }
__device__ __forceinline__ int imax(int a, int b) { return a > b ? a : b; }

// ---------------------------------------------------------------------------
// Kernel 1: 128 blocks (one wave): partial Gram over a 64-dim chunk,
// 64x32 tile, 4x2 register tiling. Blocks 0..31 additionally compute 8
// squared norms each as a short tail (one warp per row).
// ---------------------------------------------------------------------------
__global__ void gram_kernel(const float* __restrict__ features) {
    __shared__ float As[64 * 68];
    __shared__ float Bs[64 * 34];

    const int bid = blockIdx.x;
    const int tid = threadIdx.x;

    const int jt = (bid & 7) << 5;
    const int it = ((bid >> 3) & 3) << 6;
    const int ch = bid >> 5;                // 0..3

    if (bid == 0 && tid == 0) g_acc = 0.0;

    {   // A: 64 rows x 64 dims -> K-major transpose
        const int r  = tid >> 2;
        const int q0 = tid & 3;
        const int gi = it + r;
        const float* fa = &features[(((gi & 127) << 1) + (gi >> 7)) * 256 + (ch << 6)];
#pragma unroll
        for (int h = 0; h < 4; h++) {
            const int f4 = q0 + (h << 2);
            const float4 a = *(const float4*)&fa[f4 << 2];
            const int k0 = f4 << 2;
            As[(k0 + 0) * 68 + r] = a.x;
            As[(k0 + 1) * 68 + r] = a.y;
            As[(k0 + 2) * 68 + r] = a.z;
            As[(k0 + 3) * 68 + r] = a.w;
        }
    }
    {   // B: 32 rows x 64 dims -> K-major transpose
        const int r  = tid >> 3;
        const int q0 = tid & 7;
        const int gj = jt + r;
        const float* fb = &features[(((gj & 127) << 1) + (gj >> 7)) * 256 + (ch << 6)];
#pragma unroll
        for (int h = 0; h < 2; h++) {
            const int f4 = q0 + (h << 3);
            const float4 b = *(const float4*)&fb[f4 << 2];
            const int k0 = f4 << 2;
            Bs[(k0 + 0) * 34 + r] = b.x;
            Bs[(k0 + 1) * 34 + r] = b.y;
            Bs[(k0 + 2) * 34 + r] = b.z;
            Bs[(k0 + 3) * 34 + r] = b.w;
        }
    }
    __syncthreads();

    const int a4 = tid >> 4;
    const int tx = tid & 15;
    float c00 = 0, c01 = 0, c10 = 0, c11 = 0;
    float c20 = 0, c21 = 0, c30 = 0, c31 = 0;
#pragma unroll
    for (int k = 0; k < 64; k++) {
        const float4 av = *(const float4*)&As[k * 68 + (a4 << 2)];
        const float2 bv = *(const float2*)&Bs[k * 34 + (tx << 1)];
        c00 = fmaf(av.x, bv.x, c00);  c01 = fmaf(av.x, bv.y, c01);
        c10 = fmaf(av.y, bv.x, c10);  c11 = fmaf(av.y, bv.y, c11);
        c20 = fmaf(av.z, bv.x, c20);  c21 = fmaf(av.z, bv.y, c21);
        c30 = fmaf(av.w, bv.x, c30);  c31 = fmaf(av.w, bv.y, c31);
    }
    const int r0 = it + (a4 << 2);
    const int c0 = jt + (tx << 1);
    *(float2*)&g_gp[ch][(r0 + 0) * NN + c0] = make_float2(c00, c01);
    *(float2*)&g_gp[ch][(r0 + 1) * NN + c0] = make_float2(c10, c11);
    *(float2*)&g_gp[ch][(r0 + 2) * NN + c0] = make_float2(c20, c21);
    *(float2*)&g_gp[ch][(r0 + 3) * NN + c0] = make_float2(c30, c31);

    if (bid < 32) {                         // norms tail: 8 rows per block
        const int w = tid >> 5, lane = tid & 31;
        const int r = (bid << 3) + w;
        const float4* row = (const float4*)(features + ((((r & 127) << 1) + (r >> 7)) << 8));
        const float4 a = row[lane];
        const float4 b = row[lane + 32];
        float s = a.x * a.x + a.y * a.y + a.z * a.z + a.w * a.w
                + b.x * b.x + b.y * b.y + b.z * b.z + b.w * b.w;
#pragma unroll
        for (int o = 16; o; o >>= 1) s += __shfl_xor_sync(0xFFFFFFFFu, s, o);
        if (lane == 0) g_nrm[r] = s;
    }
}

// ---------------------------------------------------------------------------
// Kernel 2: 256 blocks x 256 threads (R12 shape). Critical path shortened:
//  - segmented suffix scan via warp shfl + 1 cross-warp fixup (2 barriers)
//  - per-segment rank counts via ballots (packed in sPK) replace the three
//    per-thread serial binary searches with one LDS lookup
//  Everything else (saturation + band + eq-run fixup) identical to R12.
// ---------------------------------------------------------------------------
__global__ void __launch_bounds__(256, 1)
main_kernel(const int* __restrict__ labels, float* __restrict__ out) {
    __shared__ float4 sJR[NN];     // rank-ordered {2E, q, ladf, sgnf}
    __shared__ float  sZR[NN];     // rank-ordered z
    __shared__ float  sX[NN];      // place-ordered 2E -> segmented suffix sums
    __shared__ float  sU[NN];      // place-ordered u
    __shared__ int    sPK[NN];     // per-rank packed incl. seg counts
    __shared__ int    cntL[8][16], cntK[8][32];
    __shared__ int    sumL[16], sumK[32];
    __shared__ int    histBase[16];
    __shared__ int    BP[10], CP[10], BM[10], CM[10];
    __shared__ int    sNP, sNE, sB;
    __shared__ float  sZmaxW[8], sZminW[8];
    __shared__ float  wST[8][3];   // per-warp per-seg suffix totals
    __shared__ int    wSC[8][3];   // per-warp per-seg rank counts
    __shared__ float  wsum[8];

    const int i    = blockIdx.x;
    const int tid  = threadIdx.x;
    const int lane = tid & 31;
    const int wid  = tid >> 5;
    const unsigned lt = (1u << lane) - 1u;
    const int li   = labels[i & 127];

    cntK[wid][lane] = 0;
    if (tid < 128) cntL[tid >> 4][tid & 15] = 0;
    if (tid < 24)  wST[tid / 3][tid % 3] = 0.0f;
    __syncthreads();

    // ---- phase 1: per-j basics (j = tid), coalesced; z min/max reduce ----
    float z = 0.0f, sgn = 0.0f;
    int lad = 15, key = 31;
    if (tid < MM) {
        const int c = tid + (tid >= i);
        float gij = 0.0f;
#pragma unroll
        for (int ch = 0; ch < 4; ch++) gij += g_gp[ch][i * NN + c];
        z = sqrtf(fmaxf(fmaf(-2.0f, gij, g_nrm[i] + g_nrm[c]), 0.0f));
        const int ld = li - labels[c & 127];
        lad = ld < 0 ? -ld : ld;
        key = (lad == 0) ? 0 : (ld > 0 ? lad : 16 + lad);
        sgn = (float)((ld > 0) - (ld < 0));
    }
    const unsigned mL = __match_any_sync(0xFFFFFFFFu, lad);
    const unsigned mK = __match_any_sync(0xFFFFFFFFu, key);
    const int tieL = __popc(mL & lt);
    const int tieK = __popc(mK & lt);
    cntL[wid][lad & 15] = __popc(mL);
    cntK[wid][key]      = __popc(mK);
    {
        float zx = (tid < MM) ? z : -1e30f;
        float zn = (tid < MM) ? z :  1e30f;
#pragma unroll
        for (int o = 16; o; o >>= 1) {
            zx = fmaxf(zx, __shfl_xor_sync(0xFFFFFFFFu, zx, o));
            zn = fminf(zn, __shfl_xor_sync(0xFFFFFFFFu, zn, o));
        }
        if (lane == 0) { sZmaxW[wid] = zx; sZminW[wid] = zn; }
    }
    __syncthreads();

    if (tid < 16) { int s = 0;
#pragma unroll
        for (int g = 0; g < 8; g++) s += cntL[g][tid];
        sumL[tid] = s; }
    if (tid >= 32 && tid < 64) { int s = 0; const int b = tid - 32;
#pragma unroll
        for (int g = 0; g < 8; g++) s += cntK[g][b];
        sumK[b] = s; }
    __syncthreads();

    if (tid == 0) {
        int run = 0;
#pragma unroll
        for (int b = 0; b < 16; b++) { histBase[b] = run; run += sumL[b]; }
        run = 0;
#pragma unroll
        for (int b = 1; b <= 9; b++) { BP[b] = run; CP[b] = sumK[b]; run += sumK[b]; }
        sNP = run;
#pragma unroll
        for (int b = 1; b <= 9; b++) { BM[b] = run; CM[b] = sumK[16 + b]; run += sumK[16 + b]; }
        sNE = run;
        BP[0] = 0; CP[0] = 0; BM[0] = sNP; CM[0] = 0;
        float zx = -1e30f, zn = 1e30f;
#pragma unroll
        for (int w = 0; w < 8; w++) { zx = fmaxf(zx, sZmaxW[w]); zn = fminf(zn, sZminW[w]); }
        int Bv = (int)ceilf((12.0f + 0.5f * (zx - zn)) * 0.2f) - 1;
        sB = imax(Bv, 1);
    }
    __syncthreads();

    // ---- phase 2: ranks + dual placement ----
    if (tid < MM) {
        int tl = tieL, tk = tieK;
        for (int gg = 0; gg < wid; gg++) { tl += cntL[gg][lad]; tk += cntK[gg][key]; }
        const int rank = histBase[lad] + tl;
        const float rh = 5.0f * (float)rank;     // (rank/delta)/2
        int place;
        if (key == 0)       place = sNE + tk;
        else if (key < 16)  place = BP[key] + tk;
        else                place = BM[key - 16] + tk;
        const float u = sgn * z;
        const float E2 = 2.0f * __expf(-u);
        sX[place] = E2;
        sU[place] = u;
        sJR[rank] = make_float4(E2, fmaf(-0.5f, u, rh), (float)lad, sgn);
        sZR[rank] = z;
    } else {
        sX[tid] = 0.0f;      // tid == 255 pad
    }
    __syncthreads();

    // ---- phase 2.5: warp-level segmented suffix scan + rank seg-counts ----
    const int NPc = sNP, NEc = sNE;
    {
        const int p = tid;
        float v = sX[p];
        const int segp = (p < NPc) ? 0 : ((p < NEc) ? 1 : 2);
#pragma unroll
        for (int off = 1; off < 32; off <<= 1) {
            const float t = __shfl_down_sync(0xFFFFFFFFu, v, off);
            if (lane + off < 32) {
                const int pn = p + off;
                const int segn = (pn < NPc) ? 0 : ((pn < NEc) ? 1 : 2);
                if (segn == segp) v += t;
            }
        }
        bool head = (lane == 0);
        if (!head) {
            const int pm = p - 1;
            const int segm = (pm < NPc) ? 0 : ((pm < NEc) ? 1 : 2);
            head = (segm != segp);
        }
        if (head) wST[wid][segp] = v;

        // rank-side inclusive seg counts via ballots
        int segr = 3;
        if (tid < MM) {
            const float sg = sJR[tid].w;
            segr = (sg > 0.0f) ? 0 : ((sg < 0.0f) ? 1 : 2);
        }
        const unsigned bb0 = __ballot_sync(0xFFFFFFFFu, segr == 0);
        const unsigned bb1 = __ballot_sync(0xFFFFFFFFu, segr == 1);
        const unsigned bb2 = __ballot_sync(0xFFFFFFFFu, segr == 2);
        const unsigned lemask = lt | (1u << lane);
        int c0 = __popc(bb0 & lemask);
        int c1 = __popc(bb1 & lemask);
        int c2 = __popc(bb2 & lemask);
        if (lane == 31) { wSC[wid][0] = __popc(bb0); wSC[wid][1] = __popc(bb1); wSC[wid][2] = __popc(bb2); }
        __syncthreads();

        float add = 0.0f;
        for (int w = wid + 1; w < 8; w++) add += wST[w][segp];
        sX[p] = v + add;
        for (int w = 0; w < wid; w++) { c0 += wSC[w][0]; c1 += wSC[w][1]; c2 += wSC[w][2]; }
        sPK[tid] = c0 | (c1 << 10) | (c2 << 20);
    }
    __syncthreads();

    // ---- phase 3: per k, processed in rank order (kq = rank of k) ----
    float term = 0.0f;
    if (tid < MM) {
        const int kq = tid;
        const float4 kr = sJR[kq];
        const float ladkf = kr.z;
        const int   ladk  = (int)ladkf;
        const float zk  = sZR[kq];
        const float rhk = 5.0f * (float)kq;
        const float epk = __expf(zk);
        const float enk = __expf(-zk);
        const float epkH = 0.5f * epk;
        const float enkH = 0.5f * enk;
        const int Bv = sB;

        // saturated mass (weight exactly 2) for rank >= kq + Bv + 1
        const int pk = sPK[imin(kq + Bv, MM - 1)];
        const int iP = pk & 1023;
        const int iM = NPc + ((pk >> 10) & 1023);
        const int i0 = NEc + (pk >> 20);

        float neg = 1.0f;                   // exact j==k contribution
        float pos = 0.0f;
        if (iP < NPc) neg += epk * sX[iP];
        if (iM < NEc) neg += enk * sX[iM];
        if (ladk != 0) neg += 2.0f * (float)(MM - i0);

        // exact band: ranks [kq-Bv, kq+Bv], lad != ladk (also excludes j==k)
        const float zkH = 0.5f * zk;
        const int rlo = imax(kq - Bv, 0);
        const int rhi = imin(kq + Bv, MM - 1);
        for (int r = rlo; r <= rhi; r++) {
            const float4 t = sJR[r];
            if (t.z == ladkf) continue;
            const float sel = (t.w > 0.0f) ? epkH : ((t.w < 0.0f) ? enkH : 0.5f);
            const float emd = t.x * sel;
            const float arg = fmaf(zkH, t.w, t.y - rhk);
            const float tn  = tanha(arg);
            neg += fmaf(emd, tn, emd);
        }

        // eq-lad runs: remove saturated additions, add exact pos terms
        if (ladk != 0) {
            const int loP = BP[ladk], hiP = loP + CP[ladk];
            int a = imax(loP, iP);
            if (a < hiP) {
                const float hv = (hiP < NPc) ? sX[hiP] : 0.0f;
                neg -= epk * (sX[a] - hv);
            }
            for (int p = loP; p < hiP; p++) {
                const float ad = fabsf(sU[p] - zk);
                pos += fmaf(ad, tanha(fmaf(0.5f, ad, -0.05f)), ad);
            }
            const int loM = BM[ladk], hiM = loM + CM[ladk];
            a = imax(loM, iM);
            if (a < hiM) {
                const float hv = (hiM < NEc) ? sX[hiM] : 0.0f;
                neg -= enk * (sX[a] - hv);
            }
            for (int p = loM; p < hiM; p++) {
                const float ad = fabsf(sU[p] + zk);
                pos += fmaf(ad, tanha(fmaf(0.5f, ad, -0.05f)), ad);
            }
        }
        term = pos + logf(neg);
    }

    // ---- reduce + fused finalize ----
#pragma unroll
    for (int o = 16; o; o >>= 1) term += __shfl_xor_sync(0xFFFFFFFFu, term, o);
    if (lane == 0) wsum[wid] = term;
    __syncthreads();
    if (tid == 0) {
        float s = 0.0f;
#pragma unroll
        for (int w = 0; w < 8; w++) s += wsum[w];
        atomicAdd(&g_acc, (double)s);
        __threadfence();
        const int old = atomicAdd(&g_done, 1);
        if (old == NN - 1) {                // last block finalizes
            g_done = 0;                     // reset for next graph replay
            out[0] = (float)(g_acc / (double)(NN * MM));
        }
    }
}

extern "C" void kernel_launch(void* const* d_in, const int* in_sizes, int n_in,
                              void* d_out, int out_size) {
    const float* features = (const float*)d_in[0];   // [128,2,256] f32
    const int*   labels   = (const int*)d_in[1];     // [128,1] i32
    float*       out      = (float*)d_out;           // scalar f32

    gram_kernel<<<128, 256>>>(features);
    main_kernel<<<NN, 256>>>(labels, out);
}